// round 6
// baseline (speedup 1.0000x reference)
#include <cuda_runtime.h>
#include <math.h>

#define NB   4
#define SEQ  2048
#define DIM  1024
#define NH   16
#define DKH  64
#define MTOT (NB*SEQ)        // 8192

// Scratch (device globals: no allocations allowed)
__device__ float g_q[NB*NH*SEQ*DKH];
__device__ float g_k[NB*NH*SEQ*DKH];
__device__ float g_v[NB*NH*SEQ*DKH];
__device__ float g_att[NB*NH*SEQ*DKH];
__device__ float g_cos[SEQ*(DKH/2)];
__device__ float g_sin[SEQ*(DKH/2)];

// ---------------------------------------------------------------------------
// RoPE table: cos/sin per (position, freq-pair). Double math for accuracy.
// ---------------------------------------------------------------------------
__global__ void rope_table_kernel(const int* __restrict__ pos) {
    int idx = blockIdx.x * blockDim.x + threadIdx.x;
    if (idx >= SEQ * (DKH/2)) return;
    int srow = idx >> 5;          // / 32
    int i    = idx & 31;
    double freq = exp(-((double)(2*i) / (double)DKH) * log(10000.0));
    double ang  = (double)pos[srow] * freq;
    g_cos[idx] = (float)cos(ang);
    g_sin[idx] = (float)sin(ang);
}

// ---------------------------------------------------------------------------
// Apply RoPE in place to g_q and g_k. One thread per (even,odd) pair.
// ---------------------------------------------------------------------------
__global__ void rope_apply_kernel() {
    int idx = blockIdx.x * blockDim.x + threadIdx.x;   // < 2 * NB*NH*SEQ*32 = 2^23
    int t   = idx >> 22;                               // 0 = q, 1 = k
    int r   = idx & ((1 << 22) - 1);
    int i   = r & 31;
    int row = r >> 5;                                  // (b*NH+h)*SEQ + s
    int srow = row & (SEQ - 1);
    float c = g_cos[(srow << 5) + i];
    float s = g_sin[(srow << 5) + i];
    float* p = (t ? g_k : g_q) + (row << 6) + (i << 1);
    float2 v = *(float2*)p;
    *(float2*)p = make_float2(c * v.x - s * v.y, s * v.x + c * v.y);
}

// ---------------------------------------------------------------------------
// NT SGEMM: C[m][n] = sum_k A[m][k] * W[n][k].  M=8192, N=1024, K=1024.
// 128x128 tile, BK=8, 256 threads, 8x8 per thread, reg-double-buffered loads.
// AMODE 0: A row-major.  AMODE 1: gather A from g_att ([b,h,s,dk] layout).
// CDST  0: C row-major -> Cout.  1/2/3: scatter to g_q/g_k/g_v bhsd layout.
// ---------------------------------------------------------------------------
template<int AMODE>
__device__ __forceinline__ float4 load_a4(const float* __restrict__ A, int aRow, int k) {
    if (AMODE == 0) {
        return *(const float4*)(A + aRow * DIM + k);
    } else {
        int head = k >> 6, koff = k & 63;
        int bq = aRow >> 11, srow = aRow & (SEQ - 1);
        return *(const float4*)(g_att + (((bq << 4) + head) * SEQ + srow) * DKH + koff);
    }
}

template<int AMODE, int CDST>
__global__ __launch_bounds__(256)
void gemm_nt_kernel(const float* __restrict__ A,
                    const float* __restrict__ W,
                    float* __restrict__ Cout) {
    __shared__ float As[8][128];
    __shared__ float Bs[8][128];
    const int bn = blockIdx.x;          // 0..7
    const int bm = blockIdx.y;          // 0..63
    const int tid = threadIdx.x;
    const int tx = tid & 15;
    const int ty = tid >> 4;
    const int loadRow = tid >> 1;       // 0..127
    const int loadK   = (tid & 1) << 2; // 0 or 4
    const int aRow = bm * 128 + loadRow;
    const int wRow = bn * 128 + loadRow;

    float acc[8][8];
    #pragma unroll
    for (int i = 0; i < 8; i++)
        #pragma unroll
        for (int j = 0; j < 8; j++) acc[i][j] = 0.f;

    float4 av = load_a4<AMODE>(A, aRow, loadK);
    float4 wv = *(const float4*)(W + wRow * DIM + loadK);

    for (int kt = 0; kt < DIM / 8; ++kt) {
        As[loadK + 0][loadRow] = av.x;
        As[loadK + 1][loadRow] = av.y;
        As[loadK + 2][loadRow] = av.z;
        As[loadK + 3][loadRow] = av.w;
        Bs[loadK + 0][loadRow] = wv.x;
        Bs[loadK + 1][loadRow] = wv.y;
        Bs[loadK + 2][loadRow] = wv.z;
        Bs[loadK + 3][loadRow] = wv.w;
        __syncthreads();
        if (kt + 1 < DIM / 8) {
            int k = (kt + 1) * 8 + loadK;
            av = load_a4<AMODE>(A, aRow, k);
            wv = *(const float4*)(W + wRow * DIM + k);
        }
        #pragma unroll
        for (int kk = 0; kk < 8; ++kk) {
            float4 a0 = *(const float4*)&As[kk][ty * 4];
            float4 a1 = *(const float4*)&As[kk][64 + ty * 4];
            float4 b0 = *(const float4*)&Bs[kk][tx * 4];
            float4 b1 = *(const float4*)&Bs[kk][64 + tx * 4];
            float ar[8] = {a0.x, a0.y, a0.z, a0.w, a1.x, a1.y, a1.z, a1.w};
            float br[8] = {b0.x, b0.y, b0.z, b0.w, b1.x, b1.y, b1.z, b1.w};
            #pragma unroll
            for (int i = 0; i < 8; i++)
                #pragma unroll
                for (int j = 0; j < 8; j++) acc[i][j] += ar[i] * br[j];
        }
        __syncthreads();
    }

    #pragma unroll
    for (int i = 0; i < 8; i++) {
        int r = bm * 128 + ((i < 4) ? (ty * 4 + i) : (64 + ty * 4 + (i - 4)));
        #pragma unroll
        for (int jc = 0; jc < 2; ++jc) {
            int c0 = bn * 128 + jc * 64 + tx * 4;
            float4 v = make_float4(acc[i][jc*4+0], acc[i][jc*4+1], acc[i][jc*4+2], acc[i][jc*4+3]);
            if (CDST == 0) {
                *(float4*)(Cout + r * DIM + c0) = v;
            } else {
                float* dst = (CDST == 1) ? g_q : (CDST == 2) ? g_k : g_v;
                int head = c0 >> 6, koff = c0 & 63;
                int bq = r >> 11, srow = r & (SEQ - 1);
                *(float4*)(dst + (((bq << 4) + head) * SEQ + srow) * DKH + koff) = v;
            }
        }
    }
}

// ---------------------------------------------------------------------------
// Flash attention, fp32. One block per (b*h, 64-row q tile). 256 threads.
// smem (dynamic, exactly 48KB -> no cudaFuncSetAttribute needed):
//   Qt[64][64]  Q^T  (Qt[k*64+row]), written via row-per-lane mapping
//   KPt[64][64] K^T plain; reused as P^T with XOR swizzle
//   Vs[64][64]  natural
// P^T swizzle: addr(key, r4) = key*64 + (r4 ^ (((key>>2)&7)<<2)), r4 4-aligned.
// ---------------------------------------------------------------------------
#define OUTER4(ACC, Av, Bv) \
    ACC[0][0] += Av.x*Bv.x; ACC[0][1] += Av.x*Bv.y; ACC[0][2] += Av.x*Bv.z; ACC[0][3] += Av.x*Bv.w; \
    ACC[1][0] += Av.y*Bv.x; ACC[1][1] += Av.y*Bv.y; ACC[1][2] += Av.y*Bv.z; ACC[1][3] += Av.y*Bv.w; \
    ACC[2][0] += Av.z*Bv.x; ACC[2][1] += Av.z*Bv.y; ACC[2][2] += Av.z*Bv.z; ACC[2][3] += Av.z*Bv.w; \
    ACC[3][0] += Av.w*Bv.x; ACC[3][1] += Av.w*Bv.y; ACC[3][2] += Av.w*Bv.z; ACC[3][3] += Av.w*Bv.w;

__global__ __launch_bounds__(256)
void attn_kernel() {
    extern __shared__ float sm[];
    float* Qt  = sm;                    // 4096 floats
    float* KPt = sm + 4096;             // 4096 floats
    float* Vs  = sm + 8192;             // 4096 floats
    const int qt = 31 - (int)blockIdx.x;     // heavy tiles first
    const int bh = blockIdx.y;
    const int tid = threadIdx.x;
    const int tx = tid & 15, ty = tid >> 4;

    // Load Q^T: row-per-lane mapping -> conflict-free scalar transpose stores
    const float* qb = g_q + (bh * SEQ + qt * 64) * DKH;
    #pragma unroll
    for (int it = 0; it < 4; ++it) {
        int idx = tid + it * 256;       // 0..1023
        int row = idx & 63;
        int kg  = (idx >> 6) << 2;      // 0,4,...,60
        float4 v = *(const float4*)(qb + row * DKH + kg);
        Qt[(kg + 0) * 64 + row] = v.x;
        Qt[(kg + 1) * 64 + row] = v.y;
        Qt[(kg + 2) * 64 + row] = v.z;
        Qt[(kg + 3) * 64 + row] = v.w;
    }

    float acc[4][4];
    #pragma unroll
    for (int i = 0; i < 4; i++)
        #pragma unroll
        for (int j = 0; j < 4; j++) acc[i][j] = 0.f;
    float Mr[4] = {-INFINITY, -INFINITY, -INFINITY, -INFINITY};
    float Lr[4] = {0.f, 0.f, 0.f, 0.f};
    __syncthreads();

    for (int kt = 0; kt <= qt; ++kt) {
        const float* kb = g_k + (bh * SEQ + kt * 64) * DKH;
        const float* vb = g_v + (bh * SEQ + kt * 64) * DKH;
        // K^T: row-per-lane mapping (conflict-free transpose stores)
        #pragma unroll
        for (int it = 0; it < 4; ++it) {
            int idx = tid + it * 256;
            int row = idx & 63;
            int kg  = (idx >> 6) << 2;
            float4 v = *(const float4*)(kb + row * DKH + kg);
            KPt[(kg + 0) * 64 + row] = v.x;
            KPt[(kg + 1) * 64 + row] = v.y;
            KPt[(kg + 2) * 64 + row] = v.z;
            KPt[(kg + 3) * 64 + row] = v.w;
        }
        // V: natural layout, coalesced gmem + conflict-free float4 stores
        #pragma unroll
        for (int it = 0; it < 4; ++it) {
            int idx = tid + it * 256;
            int row = idx >> 4;
            int k4  = (idx & 15) << 2;
            float4 w = *(const float4*)(vb + row * DKH + k4);
            *(float4*)&Vs[(row << 6) + k4] = w;
        }
        __syncthreads();

        // S = Q K^T  (q rows ty*4.., key cols tx*4..)
        float sc[4][4];
        #pragma unroll
        for (int i = 0; i < 4; i++)
            #pragma unroll
            for (int j = 0; j < 4; j++) sc[i][j] = 0.f;
        #pragma unroll 16
        for (int k = 0; k < 64; ++k) {
            float4 a = *(const float4*)(Qt  + k * 64 + (ty << 2));
            float4 b = *(const float4*)(KPt + k * 64 + (tx << 2));
            OUTER4(sc, a, b)
        }

        // scale + causal mask (only bites on the diagonal tile)
        const int qr0 = qt * 64 + (ty << 2);
        const int kc0 = kt * 64 + (tx << 2);
        #pragma unroll
        for (int i = 0; i < 4; i++)
            #pragma unroll
            for (int j = 0; j < 4; j++) {
                sc[i][j] *= 0.125f;
                if (kc0 + j > qr0 + i) sc[i][j] = -INFINITY;
            }

        // online softmax: row stats reduced over the 16-lane tx group
        #pragma unroll
        for (int i = 0; i < 4; i++) {
            float mt = fmaxf(fmaxf(sc[i][0], sc[i][1]), fmaxf(sc[i][2], sc[i][3]));
            #pragma unroll
            for (int o = 8; o > 0; o >>= 1)
                mt = fmaxf(mt, __shfl_xor_sync(0xffffffffu, mt, o));
            float Mn = fmaxf(Mr[i], mt);
            float al = __expf(Mr[i] - Mn);
            Mr[i] = Mn;
            float rs = 0.f;
            #pragma unroll
            for (int j = 0; j < 4; j++) {
                float p = __expf(sc[i][j] - Mn);
                sc[i][j] = p;
                rs += p;
            }
            #pragma unroll
            for (int o = 8; o > 0; o >>= 1)
                rs += __shfl_xor_sync(0xffffffffu, rs, o);
            Lr[i] = Lr[i] * al + rs;
            #pragma unroll
            for (int j = 0; j < 4; j++) acc[i][j] *= al;
        }

        __syncthreads();                 // all done reading KPt as K
        // write P^T into KPt with XOR swizzle: Pt[key][q row]
        #pragma unroll
        for (int jj = 0; jj < 4; ++jj) {
            int key = (tx << 2) + jj;
            int off = key * 64 + (((ty << 2)) ^ (((key >> 2) & 7) << 2));
            float4 pv = make_float4(sc[0][jj], sc[1][jj], sc[2][jj], sc[3][jj]);
            *(float4*)&KPt[off] = pv;
        }
        __syncthreads();

        // O += P V  (q rows ty*4.., dk cols tx*4..); swizzled P^T reads (broadcast)
        #pragma unroll 16
        for (int j = 0; j < 64; ++j) {
            float4 a = *(const float4*)(KPt + j * 64 + (((ty << 2)) ^ (((j >> 2) & 7) << 2)));
            float4 b = *(const float4*)(Vs + (j << 6) + (tx << 2));
            OUTER4(acc, a, b)
        }
        __syncthreads();                 // before next tile overwrites KPt/Vs
    }

    float* ob = g_att + (bh * SEQ + qt * 64) * DKH;
    #pragma unroll
    for (int i = 0; i < 4; i++) {
        float inv = 1.f / Lr[i];
        float4 v = make_float4(acc[i][0] * inv, acc[i][1] * inv,
                               acc[i][2] * inv, acc[i][3] * inv);
        *(float4*)(ob + ((ty << 2) + i) * DKH + (tx << 2)) = v;
    }
}

// ---------------------------------------------------------------------------
extern "C" void kernel_launch(void* const* d_in, const int* in_sizes, int n_in,
                              void* d_out, int out_size) {
    (void)in_sizes; (void)n_in; (void)out_size;
    const float* x   = (const float*)d_in[0];
    const float* Wq  = (const float*)d_in[1];
    const float* Wk  = (const float*)d_in[2];
    const float* Wv  = (const float*)d_in[3];
    const float* Wo  = (const float*)d_in[4];
    const int*   pos = (const int*)d_in[5];
    float* out = (float*)d_out;

    rope_table_kernel<<<(SEQ * 32 + 255) / 256, 256>>>(pos);

    dim3 ggrid(DIM / 128, MTOT / 128);   // (8, 64)
    gemm_nt_kernel<0, 1><<<ggrid, 256>>>(x, Wq, nullptr);
    gemm_nt_kernel<0, 2><<<ggrid, 256>>>(x, Wk, nullptr);
    gemm_nt_kernel<0, 3><<<ggrid, 256>>>(x, Wv, nullptr);

    rope_apply_kernel<<<(2 * NB * NH * SEQ * 32) / 256, 256>>>();

    // 48KB dynamic smem: within the default limit, no attribute call required.
    attn_kernel<<<dim3(SEQ / 64, NB * NH), 256, 49152>>>();

    gemm_nt_kernel<1, 0><<<ggrid, 256>>>(nullptr, Wo, out);
}

// round 8
// speedup vs baseline: 1.2353x; 1.2353x over previous
#include <cuda_runtime.h>
#include <cuda_bf16.h>
#include <mma.h>
#include <math.h>
#include <stdint.h>

using namespace nvcuda;

#define NB   4
#define SEQ  2048
#define DIM  1024
#define NH   16
#define DKH  64
#define MTOT (NB*SEQ)        // 8192

// Scratch (device globals: no allocations allowed)
__device__ float g_q[NB*NH*SEQ*DKH];
__device__ float g_k[NB*NH*SEQ*DKH];
__device__ float g_v[NB*NH*SEQ*DKH];
__device__ float g_att[NB*NH*SEQ*DKH];
__device__ float g_cos[SEQ*(DKH/2)];
__device__ float g_sin[SEQ*(DKH/2)];

// ---------------------------------------------------------------------------
// RoPE table + apply
// ---------------------------------------------------------------------------
__global__ void rope_table_kernel(const int* __restrict__ pos) {
    int idx = blockIdx.x * blockDim.x + threadIdx.x;
    if (idx >= SEQ * (DKH/2)) return;
    int srow = idx >> 5;
    int i    = idx & 31;
    double freq = exp(-((double)(2*i) / (double)DKH) * log(10000.0));
    double ang  = (double)pos[srow] * freq;
    g_cos[idx] = (float)cos(ang);
    g_sin[idx] = (float)sin(ang);
}

__global__ void rope_apply_kernel() {
    int idx = blockIdx.x * blockDim.x + threadIdx.x;
    int t   = idx >> 22;
    int r   = idx & ((1 << 22) - 1);
    int i   = r & 31;
    int row = r >> 5;
    int srow = row & (SEQ - 1);
    float c = g_cos[(srow << 5) + i];
    float s = g_sin[(srow << 5) + i];
    float* p = (t ? g_k : g_q) + (row << 6) + (i << 1);
    float2 v = *(float2*)p;
    *(float2*)p = make_float2(c * v.x - s * v.y, s * v.x + c * v.y);
}

// ---------------------------------------------------------------------------
// Split helpers: fp32 -> bf16 hi + bf16 lo (residual)
// ---------------------------------------------------------------------------
__device__ __forceinline__ uint32_t bf2(float lo, float hi) {
    uint32_t r;
    asm("cvt.rn.bf16x2.f32 %0, %1, %2;" : "=r"(r) : "f"(hi), "f"(lo));
    return r;
}

// split float4 into hi/lo bf16x2 pairs and store at u32 word offset w
__device__ __forceinline__ void split_store(uint32_t* ph, uint32_t* pl,
                                            int w, float4 v) {
    uint32_t hxy = bf2(v.x, v.y);
    uint32_t hzw = bf2(v.z, v.w);
    float fx = __uint_as_float(hxy << 16);
    float fy = __uint_as_float(hxy & 0xffff0000u);
    float fz = __uint_as_float(hzw << 16);
    float fw = __uint_as_float(hzw & 0xffff0000u);
    uint32_t lxy = bf2(v.x - fx, v.y - fy);
    uint32_t lzw = bf2(v.z - fz, v.w - fw);
    ph[w]     = hxy;
    ph[w + 1] = hzw;
    pl[w]     = lxy;
    pl[w + 1] = lzw;
}

// ---------------------------------------------------------------------------
// WMMA NT GEMM, split-bf16 x3 passes: C[m][n] = sum_k A[m][k] * W[n][k]
// M=8192, N=1024, K=1024. Block 128x128, BK=32, 8 warps, warp tile 32x64.
// smem planes Ah/Al/Bh/Bl: 128 rows x 32 cols bf16, stride 40 (conflict-free
// ldmatrix row bases). 40KB static smem.
// AMODE 0: A row-major. AMODE 1: gather from g_att ([b,h,s,dk] layout).
// CDST 0: row-major Cout. 1/2/3: scatter to g_q/g_k/g_v bhsd layout.
// ---------------------------------------------------------------------------
#define LDAB 40   // bf16 elements per smem row

template<int AMODE>
__device__ __forceinline__ float4 ld_a4(const float* __restrict__ A, int aRow, int k) {
    if (AMODE == 0) {
        return *(const float4*)(A + aRow * DIM + k);
    } else {
        int head = k >> 6, koff = k & 63;
        int bq = aRow >> 11, srow = aRow & (SEQ - 1);
        return *(const float4*)(g_att + (((bq << 4) + head) * SEQ + srow) * DKH + koff);
    }
}

template<int AMODE, int CDST>
__global__ __launch_bounds__(256)
void gemm_wmma_kernel(const float* __restrict__ A,
                      const float* __restrict__ W,
                      float* __restrict__ Cout) {
    __shared__ __align__(16) uint32_t sAh[128 * LDAB / 2];
    __shared__ __align__(16) uint32_t sAl[128 * LDAB / 2];
    __shared__ __align__(16) uint32_t sBh[128 * LDAB / 2];
    __shared__ __align__(16) uint32_t sBl[128 * LDAB / 2];

    const int bn  = blockIdx.x;          // 0..7
    const int bm  = blockIdx.y;          // 0..63
    const int tid = threadIdx.x;
    const int wid = tid >> 5;
    const int wm  = wid & 3;             // warp row: 4 x 32
    const int wn  = wid >> 2;            // warp col: 2 x 64

    typedef wmma::fragment<wmma::matrix_a, 16, 16, 16, __nv_bfloat16, wmma::row_major> FragA;
    typedef wmma::fragment<wmma::matrix_b, 16, 16, 16, __nv_bfloat16, wmma::col_major> FragB;
    typedef wmma::fragment<wmma::accumulator, 16, 16, 16, float> FragC;

    FragC acc[2][4];
    #pragma unroll
    for (int i = 0; i < 2; i++)
        #pragma unroll
        for (int j = 0; j < 4; j++) wmma::fill_fragment(acc[i][j], 0.0f);

    const __nv_bfloat16* pAh = (const __nv_bfloat16*)sAh;
    const __nv_bfloat16* pAl = (const __nv_bfloat16*)sAl;
    const __nv_bfloat16* pBh = (const __nv_bfloat16*)sBh;
    const __nv_bfloat16* pBl = (const __nv_bfloat16*)sBl;

    for (int kt = 0; kt < DIM / 32; ++kt) {
        // fill A planes: 128 rows x 32 cols -> 1024 float4, 4 per thread
        #pragma unroll
        for (int j = 0; j < 4; ++j) {
            int c   = tid + j * 256;
            int row = c >> 3;
            int k4  = c & 7;
            float4 v = ld_a4<AMODE>(A, bm * 128 + row, kt * 32 + k4 * 4);
            split_store(sAh, sAl, row * (LDAB / 2) + k4 * 2, v);
        }
        // fill B planes from W[bn*128 + row][kt*32 + ...]
        #pragma unroll
        for (int j = 0; j < 4; ++j) {
            int c   = tid + j * 256;
            int row = c >> 3;
            int k4  = c & 7;
            float4 v = *(const float4*)(W + (bn * 128 + row) * DIM + kt * 32 + k4 * 4);
            split_store(sBh, sBl, row * (LDAB / 2) + k4 * 2, v);
        }
        __syncthreads();

        #pragma unroll
        for (int ks = 0; ks < 2; ++ks) {
            FragA ah[2], al[2];
            #pragma unroll
            for (int i = 0; i < 2; i++) {
                wmma::load_matrix_sync(ah[i], pAh + (wm * 32 + i * 16) * LDAB + ks * 16, LDAB);
                wmma::load_matrix_sync(al[i], pAl + (wm * 32 + i * 16) * LDAB + ks * 16, LDAB);
            }
            #pragma unroll
            for (int j = 0; j < 4; j++) {
                FragB bh, bl;
                wmma::load_matrix_sync(bh, pBh + (wn * 64 + j * 16) * LDAB + ks * 16, LDAB);
                wmma::load_matrix_sync(bl, pBl + (wn * 64 + j * 16) * LDAB + ks * 16, LDAB);
                #pragma unroll
                for (int i = 0; i < 2; i++) {
                    wmma::mma_sync(acc[i][j], ah[i], bh, acc[i][j]);
                    wmma::mma_sync(acc[i][j], ah[i], bl, acc[i][j]);
                    wmma::mma_sync(acc[i][j], al[i], bh, acc[i][j]);
                }
            }
        }
        __syncthreads();
    }

    // epilogue
    #pragma unroll
    for (int i = 0; i < 2; i++) {
        int r0 = bm * 128 + wm * 32 + i * 16;
        #pragma unroll
        for (int j = 0; j < 4; j++) {
            int c0 = bn * 128 + wn * 64 + j * 16;
            if (CDST == 0) {
                wmma::store_matrix_sync(Cout + r0 * DIM + c0, acc[i][j], DIM,
                                        wmma::mem_row_major);
            } else {
                float* base = (CDST == 1) ? g_q : (CDST == 2) ? g_k : g_v;
                int head = c0 >> 6, koff = c0 & 63;
                int bq = r0 >> 11, srow = r0 & (SEQ - 1);
                wmma::store_matrix_sync(
                    base + (((bq << 4) + head) * SEQ + srow) * DKH + koff,
                    acc[i][j], DKH, wmma::mem_row_major);
            }
        }
    }
}

// ---------------------------------------------------------------------------
// Flash attention, fp32 (unchanged — passed at rel_err 5.6e-7)
// ---------------------------------------------------------------------------
#define OUTER4(ACC, Av, Bv) \
    ACC[0][0] += Av.x*Bv.x; ACC[0][1] += Av.x*Bv.y; ACC[0][2] += Av.x*Bv.z; ACC[0][3] += Av.x*Bv.w; \
    ACC[1][0] += Av.y*Bv.x; ACC[1][1] += Av.y*Bv.y; ACC[1][2] += Av.y*Bv.z; ACC[1][3] += Av.y*Bv.w; \
    ACC[2][0] += Av.z*Bv.x; ACC[2][1] += Av.z*Bv.y; ACC[2][2] += Av.z*Bv.z; ACC[2][3] += Av.z*Bv.w; \
    ACC[3][0] += Av.w*Bv.x; ACC[3][1] += Av.w*Bv.y; ACC[3][2] += Av.w*Bv.z; ACC[3][3] += Av.w*Bv.w;

__global__ __launch_bounds__(256)
void attn_kernel() {
    extern __shared__ float smf[];
    float* Qt  = smf;
    float* KPt = smf + 4096;
    float* Vs  = smf + 8192;
    const int qt = 31 - (int)blockIdx.x;
    const int bh = blockIdx.y;
    const int tid = threadIdx.x;
    const int tx = tid & 15, ty = tid >> 4;

    const float* qb = g_q + (bh * SEQ + qt * 64) * DKH;
    #pragma unroll
    for (int it = 0; it < 4; ++it) {
        int idx = tid + it * 256;
        int row = idx & 63;
        int kg  = (idx >> 6) << 2;
        float4 v = *(const float4*)(qb + row * DKH + kg);
        Qt[(kg + 0) * 64 + row] = v.x;
        Qt[(kg + 1) * 64 + row] = v.y;
        Qt[(kg + 2) * 64 + row] = v.z;
        Qt[(kg + 3) * 64 + row] = v.w;
    }

    float acc[4][4];
    #pragma unroll
    for (int i = 0; i < 4; i++)
        #pragma unroll
        for (int j = 0; j < 4; j++) acc[i][j] = 0.f;
    float Mr[4] = {-INFINITY, -INFINITY, -INFINITY, -INFINITY};
    float Lr[4] = {0.f, 0.f, 0.f, 0.f};
    __syncthreads();

    for (int kt = 0; kt <= qt; ++kt) {
        const float* kb = g_k + (bh * SEQ + kt * 64) * DKH;
        const float* vb = g_v + (bh * SEQ + kt * 64) * DKH;
        #pragma unroll
        for (int it = 0; it < 4; ++it) {
            int idx = tid + it * 256;
            int row = idx & 63;
            int kg  = (idx >> 6) << 2;
            float4 v = *(const float4*)(kb + row * DKH + kg);
            KPt[(kg + 0) * 64 + row] = v.x;
            KPt[(kg + 1) * 64 + row] = v.y;
            KPt[(kg + 2) * 64 + row] = v.z;
            KPt[(kg + 3) * 64 + row] = v.w;
        }
        #pragma unroll
        for (int it = 0; it < 4; ++it) {
            int idx = tid + it * 256;
            int row = idx >> 4;
            int k4  = (idx & 15) << 2;
            float4 w = *(const float4*)(vb + row * DKH + k4);
            *(float4*)&Vs[(row << 6) + k4] = w;
        }
        __syncthreads();

        float sc[4][4];
        #pragma unroll
        for (int i = 0; i < 4; i++)
            #pragma unroll
            for (int j = 0; j < 4; j++) sc[i][j] = 0.f;
        #pragma unroll 16
        for (int k = 0; k < 64; ++k) {
            float4 a = *(const float4*)(Qt  + k * 64 + (ty << 2));
            float4 b = *(const float4*)(KPt + k * 64 + (tx << 2));
            OUTER4(sc, a, b)
        }

        const int qr0 = qt * 64 + (ty << 2);
        const int kc0 = kt * 64 + (tx << 2);
        #pragma unroll
        for (int i = 0; i < 4; i++)
            #pragma unroll
            for (int j = 0; j < 4; j++) {
                sc[i][j] *= 0.125f;
                if (kc0 + j > qr0 + i) sc[i][j] = -INFINITY;
            }

        #pragma unroll
        for (int i = 0; i < 4; i++) {
            float mt = fmaxf(fmaxf(sc[i][0], sc[i][1]), fmaxf(sc[i][2], sc[i][3]));
            #pragma unroll
            for (int o = 8; o > 0; o >>= 1)
                mt = fmaxf(mt, __shfl_xor_sync(0xffffffffu, mt, o));
            float Mn = fmaxf(Mr[i], mt);
            float al = __expf(Mr[i] - Mn);
            Mr[i] = Mn;
            float rs = 0.f;
            #pragma unroll
            for (int j = 0; j < 4; j++) {
                float p = __expf(sc[i][j] - Mn);
                sc[i][j] = p;
                rs += p;
            }
            #pragma unroll
            for (int o = 8; o > 0; o >>= 1)
                rs += __shfl_xor_sync(0xffffffffu, rs, o);
            Lr[i] = Lr[i] * al + rs;
            #pragma unroll
            for (int j = 0; j < 4; j++) acc[i][j] *= al;
        }

        __syncthreads();
        #pragma unroll
        for (int jj = 0; jj < 4; ++jj) {
            int key = (tx << 2) + jj;
            int off = key * 64 + (((ty << 2)) ^ (((key >> 2) & 7) << 2));
            float4 pv = make_float4(sc[0][jj], sc[1][jj], sc[2][jj], sc[3][jj]);
            *(float4*)&KPt[off] = pv;
        }
        __syncthreads();

        #pragma unroll 16
        for (int j = 0; j < 64; ++j) {
            float4 a = *(const float4*)(KPt + j * 64 + (((ty << 2)) ^ (((j >> 2) & 7) << 2)));
            float4 b = *(const float4*)(Vs + (j << 6) + (tx << 2));
            OUTER4(acc, a, b)
        }
        __syncthreads();
    }

    float* ob = g_att + (bh * SEQ + qt * 64) * DKH;
    #pragma unroll
    for (int i = 0; i < 4; i++) {
        float inv = 1.f / Lr[i];
        float4 v = make_float4(acc[i][0] * inv, acc[i][1] * inv,
                               acc[i][2] * inv, acc[i][3] * inv);
        *(float4*)(ob + ((ty << 2) + i) * DKH + (tx << 2)) = v;
    }
}

// ---------------------------------------------------------------------------
extern "C" void kernel_launch(void* const* d_in, const int* in_sizes, int n_in,
                              void* d_out, int out_size) {
    (void)in_sizes; (void)n_in; (void)out_size;
    const float* x   = (const float*)d_in[0];
    const float* Wq  = (const float*)d_in[1];
    const float* Wk  = (const float*)d_in[2];
    const float* Wv  = (const float*)d_in[3];
    const float* Wo  = (const float*)d_in[4];
    const int*   pos = (const int*)d_in[5];
    float* out = (float*)d_out;

    rope_table_kernel<<<(SEQ * 32 + 255) / 256, 256>>>(pos);

    dim3 ggrid(DIM / 128, MTOT / 128);   // (8, 64)
    gemm_wmma_kernel<0, 1><<<ggrid, 256>>>(x, Wq, nullptr);
    gemm_wmma_kernel<0, 2><<<ggrid, 256>>>(x, Wk, nullptr);
    gemm_wmma_kernel<0, 3><<<ggrid, 256>>>(x, Wv, nullptr);

    rope_apply_kernel<<<(2 * NB * NH * SEQ * 32) / 256, 256>>>();

    attn_kernel<<<dim3(SEQ / 64, NB * NH), 256, 49152>>>();

    gemm_wmma_kernel<1, 0><<<ggrid, 256>>>(nullptr, Wo, out);
}

// round 9
// speedup vs baseline: 1.6151x; 1.3074x over previous
#include <cuda_runtime.h>
#include <cuda_bf16.h>
#include <mma.h>
#include <math.h>
#include <stdint.h>

using namespace nvcuda;

#define NB   4
#define SEQ  2048
#define DIM  1024
#define NH   16
#define DKH  64
#define MTOT (NB*SEQ)        // 8192

// Scratch (device globals: no allocations allowed)
__device__ float g_q[NB*NH*SEQ*DKH];
__device__ float g_k[NB*NH*SEQ*DKH];
__device__ float g_v[NB*NH*SEQ*DKH];
__device__ float g_att[NB*NH*SEQ*DKH];
__device__ float g_cos[SEQ*(DKH/2)];
__device__ float g_sin[SEQ*(DKH/2)];

// ---------------------------------------------------------------------------
// RoPE table + apply
// ---------------------------------------------------------------------------
__global__ void rope_table_kernel(const int* __restrict__ pos) {
    int idx = blockIdx.x * blockDim.x + threadIdx.x;
    if (idx >= SEQ * (DKH/2)) return;
    int srow = idx >> 5;
    int i    = idx & 31;
    double freq = exp(-((double)(2*i) / (double)DKH) * log(10000.0));
    double ang  = (double)pos[srow] * freq;
    g_cos[idx] = (float)cos(ang);
    g_sin[idx] = (float)sin(ang);
}

__global__ void rope_apply_kernel() {
    int idx = blockIdx.x * blockDim.x + threadIdx.x;
    int t   = idx >> 22;
    int r   = idx & ((1 << 22) - 1);
    int i   = r & 31;
    int row = r >> 5;
    int srow = row & (SEQ - 1);
    float c = g_cos[(srow << 5) + i];
    float s = g_sin[(srow << 5) + i];
    float* p = (t ? g_k : g_q) + (row << 6) + (i << 1);
    float2 v = *(float2*)p;
    *(float2*)p = make_float2(c * v.x - s * v.y, s * v.x + c * v.y);
}

// ---------------------------------------------------------------------------
// Split helpers: fp32 -> bf16 hi + bf16 lo (residual)
// ---------------------------------------------------------------------------
__device__ __forceinline__ uint32_t bf2(float lo, float hi) {
    uint32_t r;
    asm("cvt.rn.bf16x2.f32 %0, %1, %2;" : "=r"(r) : "f"(hi), "f"(lo));
    return r;
}

__device__ __forceinline__ void split_store(uint32_t* ph, uint32_t* pl,
                                            int w, float4 v) {
    uint32_t hxy = bf2(v.x, v.y);
    uint32_t hzw = bf2(v.z, v.w);
    float fx = __uint_as_float(hxy << 16);
    float fy = __uint_as_float(hxy & 0xffff0000u);
    float fz = __uint_as_float(hzw << 16);
    float fw = __uint_as_float(hzw & 0xffff0000u);
    uint32_t lxy = bf2(v.x - fx, v.y - fy);
    uint32_t lzw = bf2(v.z - fz, v.w - fw);
    ph[w]     = hxy;
    ph[w + 1] = hzw;
    pl[w]     = lxy;
    pl[w + 1] = lzw;
}

// ---------------------------------------------------------------------------
// WMMA NT GEMM, split-bf16 x3 passes (as R8) + 2-CTA/SM occupancy bound.
// ---------------------------------------------------------------------------
#define LDAB 40   // bf16 elements per smem row

template<int AMODE>
__device__ __forceinline__ float4 ld_a4(const float* __restrict__ A, int aRow, int k) {
    if (AMODE == 0) {
        return *(const float4*)(A + aRow * DIM + k);
    } else {
        int head = k >> 6, koff = k & 63;
        int bq = aRow >> 11, srow = aRow & (SEQ - 1);
        return *(const float4*)(g_att + (((bq << 4) + head) * SEQ + srow) * DKH + koff);
    }
}

template<int AMODE, int CDST>
__global__ __launch_bounds__(256, 2)
void gemm_wmma_kernel(const float* __restrict__ A,
                      const float* __restrict__ W,
                      float* __restrict__ Cout) {
    __shared__ __align__(16) uint32_t sAh[128 * LDAB / 2];
    __shared__ __align__(16) uint32_t sAl[128 * LDAB / 2];
    __shared__ __align__(16) uint32_t sBh[128 * LDAB / 2];
    __shared__ __align__(16) uint32_t sBl[128 * LDAB / 2];

    const int bn  = blockIdx.x;
    const int bm  = blockIdx.y;
    const int tid = threadIdx.x;
    const int wid = tid >> 5;
    const int wm  = wid & 3;
    const int wn  = wid >> 2;

    typedef wmma::fragment<wmma::matrix_a, 16, 16, 16, __nv_bfloat16, wmma::row_major> FragA;
    typedef wmma::fragment<wmma::matrix_b, 16, 16, 16, __nv_bfloat16, wmma::col_major> FragB;
    typedef wmma::fragment<wmma::accumulator, 16, 16, 16, float> FragC;

    FragC acc[2][4];
    #pragma unroll
    for (int i = 0; i < 2; i++)
        #pragma unroll
        for (int j = 0; j < 4; j++) wmma::fill_fragment(acc[i][j], 0.0f);

    const __nv_bfloat16* pAh = (const __nv_bfloat16*)sAh;
    const __nv_bfloat16* pAl = (const __nv_bfloat16*)sAl;
    const __nv_bfloat16* pBh = (const __nv_bfloat16*)sBh;
    const __nv_bfloat16* pBl = (const __nv_bfloat16*)sBl;

    for (int kt = 0; kt < DIM / 32; ++kt) {
        #pragma unroll
        for (int j = 0; j < 4; ++j) {
            int c   = tid + j * 256;
            int row = c >> 3;
            int k4  = c & 7;
            float4 v = ld_a4<AMODE>(A, bm * 128 + row, kt * 32 + k4 * 4);
            split_store(sAh, sAl, row * (LDAB / 2) + k4 * 2, v);
        }
        #pragma unroll
        for (int j = 0; j < 4; ++j) {
            int c   = tid + j * 256;
            int row = c >> 3;
            int k4  = c & 7;
            float4 v = *(const float4*)(W + (bn * 128 + row) * DIM + kt * 32 + k4 * 4);
            split_store(sBh, sBl, row * (LDAB / 2) + k4 * 2, v);
        }
        __syncthreads();

        #pragma unroll
        for (int ks = 0; ks < 2; ++ks) {
            FragA ah[2], al[2];
            #pragma unroll
            for (int i = 0; i < 2; i++) {
                wmma::load_matrix_sync(ah[i], pAh + (wm * 32 + i * 16) * LDAB + ks * 16, LDAB);
                wmma::load_matrix_sync(al[i], pAl + (wm * 32 + i * 16) * LDAB + ks * 16, LDAB);
            }
            #pragma unroll
            for (int j = 0; j < 4; j++) {
                FragB bh, bl;
                wmma::load_matrix_sync(bh, pBh + (wn * 64 + j * 16) * LDAB + ks * 16, LDAB);
                wmma::load_matrix_sync(bl, pBl + (wn * 64 + j * 16) * LDAB + ks * 16, LDAB);
                #pragma unroll
                for (int i = 0; i < 2; i++) {
                    wmma::mma_sync(acc[i][j], ah[i], bh, acc[i][j]);
                    wmma::mma_sync(acc[i][j], ah[i], bl, acc[i][j]);
                    wmma::mma_sync(acc[i][j], al[i], bh, acc[i][j]);
                }
            }
        }
        __syncthreads();
    }

    #pragma unroll
    for (int i = 0; i < 2; i++) {
        int r0 = bm * 128 + wm * 32 + i * 16;
        #pragma unroll
        for (int j = 0; j < 4; j++) {
            int c0 = bn * 128 + wn * 64 + j * 16;
            if (CDST == 0) {
                wmma::store_matrix_sync(Cout + r0 * DIM + c0, acc[i][j], DIM,
                                        wmma::mem_row_major);
            } else {
                float* base = (CDST == 1) ? g_q : (CDST == 2) ? g_k : g_v;
                int head = c0 >> 6, koff = c0 & 63;
                int bq = r0 >> 11, srow = r0 & (SEQ - 1);
                wmma::store_matrix_sync(
                    base + (((bq << 4) + head) * SEQ + srow) * DKH + koff,
                    acc[i][j], DKH, wmma::mem_row_major);
            }
        }
    }
}

// ---------------------------------------------------------------------------
// WMMA flash attention, split-bf16 x3 for QK^T and PV; fp32 softmax + O in smem.
// Block: 128 threads (4 warps). Tile: 32 q-rows x 32 keys/iter, dk=64.
// smem 40KB static: Qh/Ql, Kh/Kl (reused as Ph/Pl), Vh/Vl (stride 72 bf16),
//                   S f32 (stride 36), O f32 (stride 68).
// Softmax/rescale/epilogue use explicit thread indexing (4 threads per row),
// fragments touch smem only via load/store_matrix_sync -> no layout assumptions.
// ---------------------------------------------------------------------------
#define PSTR 72
#define SSTR 36
#define OSTR 68

__global__ __launch_bounds__(128)
void attn_wmma_kernel() {
    __shared__ __align__(16) __nv_bfloat16 sQh[32*PSTR], sQl[32*PSTR];
    __shared__ __align__(16) __nv_bfloat16 sKh[32*PSTR], sKl[32*PSTR];
    __shared__ __align__(16) __nv_bfloat16 sVh[32*PSTR], sVl[32*PSTR];
    __shared__ __align__(16) float sS[32*SSTR];
    __shared__ __align__(16) float sO[32*OSTR];

    const int qt  = 63 - (int)blockIdx.x;   // heavy q-tiles first
    const int bh  = blockIdx.y;
    const int tid = threadIdx.x;
    const int wid = tid >> 5;
    const int wm  = wid & 1;                // S row-half / O row-half
    const int wn  = wid >> 1;               // S col-half / O col-half

    typedef wmma::fragment<wmma::matrix_a, 16, 16, 16, __nv_bfloat16, wmma::row_major> FragA;
    typedef wmma::fragment<wmma::matrix_b, 16, 16, 16, __nv_bfloat16, wmma::col_major> FragBT;
    typedef wmma::fragment<wmma::matrix_b, 16, 16, 16, __nv_bfloat16, wmma::row_major> FragBN;
    typedef wmma::fragment<wmma::accumulator, 16, 16, 16, float> FragC;

    // load Q tile (32x64) split into hi/lo planes
    const float* qb = g_q + (bh * SEQ + qt * 32) * DKH;
    #pragma unroll
    for (int j = 0; j < 4; ++j) {
        int c   = tid + j * 128;            // 0..511
        int row = c >> 4, k4 = c & 15;
        float4 v = *(const float4*)(qb + row * DKH + k4 * 4);
        split_store((uint32_t*)sQh, (uint32_t*)sQl, row * (PSTR/2) + k4 * 2, v);
    }
    // zero O (32x68)
    #pragma unroll
    for (int j = 0; j < 17; ++j) sO[tid + j * 128] = 0.f;

    const int r  = tid >> 2;                // softmax row (0..31)
    const int tc = tid & 3;                 // 8-col group within row
    float M = -INFINITY, L = 0.f;
    __syncthreads();

    for (int kt = 0; kt <= qt; ++kt) {
        // load K,V tiles (32x64 each) split
        const float* kb = g_k + (bh * SEQ + kt * 32) * DKH;
        const float* vb = g_v + (bh * SEQ + kt * 32) * DKH;
        #pragma unroll
        for (int j = 0; j < 4; ++j) {
            int c   = tid + j * 128;
            int row = c >> 4, k4 = c & 15;
            float4 v = *(const float4*)(kb + row * DKH + k4 * 4);
            split_store((uint32_t*)sKh, (uint32_t*)sKl, row * (PSTR/2) + k4 * 2, v);
            float4 w = *(const float4*)(vb + row * DKH + k4 * 4);
            split_store((uint32_t*)sVh, (uint32_t*)sVl, row * (PSTR/2) + k4 * 2, w);
        }
        __syncthreads();

        // S = Q K^T : warp (wm, wn) computes 16x16 S sub-tile
        {
            FragC sf;
            wmma::fill_fragment(sf, 0.f);
            #pragma unroll
            for (int ks = 0; ks < 4; ++ks) {
                FragA qh, ql;
                FragBT kh, kl;
                wmma::load_matrix_sync(qh, sQh + wm * 16 * PSTR + ks * 16, PSTR);
                wmma::load_matrix_sync(ql, sQl + wm * 16 * PSTR + ks * 16, PSTR);
                wmma::load_matrix_sync(kh, sKh + wn * 16 * PSTR + ks * 16, PSTR);
                wmma::load_matrix_sync(kl, sKl + wn * 16 * PSTR + ks * 16, PSTR);
                wmma::mma_sync(sf, qh, kh, sf);
                wmma::mma_sync(sf, qh, kl, sf);
                wmma::mma_sync(sf, ql, kh, sf);
            }
            wmma::store_matrix_sync(sS + wm * 16 * SSTR + wn * 16, sf, SSTR,
                                    wmma::mem_row_major);
        }
        __syncthreads();

        // online softmax: 4 threads per row, 8 cols each
        float p[8];
        const int qglob = qt * 32 + r;
        const int c0 = tc * 8;
        float mloc = -INFINITY;
        #pragma unroll
        for (int i = 0; i < 8; ++i) {
            float s = sS[r * SSTR + c0 + i] * 0.125f;
            if (kt * 32 + c0 + i > qglob) s = -INFINITY;
            p[i] = s;
            mloc = fmaxf(mloc, s);
        }
        mloc = fmaxf(mloc, __shfl_xor_sync(0xffffffffu, mloc, 1));
        mloc = fmaxf(mloc, __shfl_xor_sync(0xffffffffu, mloc, 2));
        float Mn = fmaxf(M, mloc);
        float al = __expf(M - Mn);
        M = Mn;
        float rs = 0.f;
        #pragma unroll
        for (int i = 0; i < 8; ++i) { p[i] = __expf(p[i] - Mn); rs += p[i]; }
        rs += __shfl_xor_sync(0xffffffffu, rs, 1);
        rs += __shfl_xor_sync(0xffffffffu, rs, 2);
        L = L * al + rs;

        // write P split into the (now free) K planes
        #pragma unroll
        for (int i = 0; i < 4; ++i) {
            uint32_t h = bf2(p[2*i], p[2*i+1]);
            float fx = __uint_as_float(h << 16);
            float fy = __uint_as_float(h & 0xffff0000u);
            uint32_t lo = bf2(p[2*i] - fx, p[2*i+1] - fy);
            ((uint32_t*)sKh)[r * (PSTR/2) + tc * 4 + i] = h;
            ((uint32_t*)sKl)[r * (PSTR/2) + tc * 4 + i] = lo;
        }
        // rescale O row by al (thread owns row r, cols tc*16..tc*16+15)
        #pragma unroll
        for (int i = 0; i < 4; ++i) {
            float4* po = (float4*)&sO[r * OSTR + tc * 16 + i * 4];
            float4 v = *po;
            v.x *= al; v.y *= al; v.z *= al; v.w *= al;
            *po = v;
        }
        __syncthreads();

        // O += P V : warp (wm, wn) computes O[wm*16.., wn*32..] (2 frags)
        {
            FragC of[2];
            #pragma unroll
            for (int j = 0; j < 2; ++j)
                wmma::load_matrix_sync(of[j], sO + wm * 16 * OSTR + wn * 32 + j * 16,
                                       OSTR, wmma::mem_row_major);
            #pragma unroll
            for (int ks = 0; ks < 2; ++ks) {
                FragA ph, pl;
                wmma::load_matrix_sync(ph, sKh + wm * 16 * PSTR + ks * 16, PSTR);
                wmma::load_matrix_sync(pl, sKl + wm * 16 * PSTR + ks * 16, PSTR);
                #pragma unroll
                for (int j = 0; j < 2; ++j) {
                    FragBN vh, vl;
                    wmma::load_matrix_sync(vh, sVh + ks * 16 * PSTR + wn * 32 + j * 16, PSTR);
                    wmma::load_matrix_sync(vl, sVl + ks * 16 * PSTR + wn * 32 + j * 16, PSTR);
                    wmma::mma_sync(of[j], ph, vh, of[j]);
                    wmma::mma_sync(of[j], ph, vl, of[j]);
                    wmma::mma_sync(of[j], pl, vh, of[j]);
                }
            }
            #pragma unroll
            for (int j = 0; j < 2; ++j)
                wmma::store_matrix_sync(sO + wm * 16 * OSTR + wn * 32 + j * 16, of[j],
                                        OSTR, wmma::mem_row_major);
        }
        __syncthreads();
    }

    // epilogue: normalize by L and write out
    float inv = 1.f / L;
    float* ob = g_att + (bh * SEQ + qt * 32) * DKH;
    #pragma unroll
    for (int i = 0; i < 4; ++i) {
        float4 v = *(float4*)&sO[r * OSTR + tc * 16 + i * 4];
        v.x *= inv; v.y *= inv; v.z *= inv; v.w *= inv;
        *(float4*)(ob + r * DKH + tc * 16 + i * 4) = v;
    }
}

// ---------------------------------------------------------------------------
extern "C" void kernel_launch(void* const* d_in, const int* in_sizes, int n_in,
                              void* d_out, int out_size) {
    (void)in_sizes; (void)n_in; (void)out_size;
    const float* x   = (const float*)d_in[0];
    const float* Wq  = (const float*)d_in[1];
    const float* Wk  = (const float*)d_in[2];
    const float* Wv  = (const float*)d_in[3];
    const float* Wo  = (const float*)d_in[4];
    const int*   pos = (const int*)d_in[5];
    float* out = (float*)d_out;

    rope_table_kernel<<<(SEQ * 32 + 255) / 256, 256>>>(pos);

    dim3 ggrid(DIM / 128, MTOT / 128);   // (8, 64)
    gemm_wmma_kernel<0, 1><<<ggrid, 256>>>(x, Wq, nullptr);
    gemm_wmma_kernel<0, 2><<<ggrid, 256>>>(x, Wk, nullptr);
    gemm_wmma_kernel<0, 3><<<ggrid, 256>>>(x, Wv, nullptr);

    rope_apply_kernel<<<(2 * NB * NH * SEQ * 32) / 256, 256>>>();

    attn_wmma_kernel<<<dim3(SEQ / 32, NB * NH), 128>>>();

    gemm_wmma_kernel<1, 0><<<ggrid, 256>>>(nullptr, Wo, out);
}